// round 4
// baseline (speedup 1.0000x reference)
#include <cuda_runtime.h>
#include <math.h>
#include <stdint.h>

#define NIMG 8
#define KMIX 5
#define RTOT 96000
#define NGT 32
#define PRE 2000
#define POST 1000
#define MASKW 63            // ceil(2000/32)
#define BPI (RTOT/256)      // blocks per image at 256 threads = 375
#define IMGSZ 1280.0f
#define SCALE_CLAMP 4.135166556742356f   /* log(1000/16) */
#define HALF_LOG2PI 0.9189385332046727f  /* 0.5*log(2*pi) */
#define NMS_T 0.7f

// correctly-rounded float exp/log via double (matches glibc-class reference libm)
__device__ __forceinline__ float cr_expf(float x){ return (float)exp((double)x); }
__device__ __forceinline__ float cr_logf(float x){ return (float)log((double)x); }

// ---------------- static device scratch (no allocs allowed) ----------------
__device__ float g_logits[NIMG*RTOT];
__device__ float g_unc[NIMG*RTOT*2];
__device__ float g_boxes[NIMG*RTOT*4];
__device__ unsigned g_keys[NIMG*RTOT];
__device__ float g_vals[NIMG*RTOT];
__device__ int   g_gidx[NIMG*RTOT];
__device__ unsigned g_bestgt[NIMG*NGT];
__device__ signed char g_lab0[NIMG*RTOT];
__device__ unsigned g_hist[4*NIMG*256];
__device__ unsigned g_prefix[NIMG];
__device__ int g_need[NIMG];
__device__ int g_cntgt[NIMG];
__device__ int g_cnteq[NIMG];
__device__ unsigned long long g_sel[NIMG*2048];
__device__ int g_eq[NIMG*4096];
__device__ int   g_tidx[NIMG*PRE];
__device__ float g_ts[NIMG*PRE];
__device__ float g_tb[NIMG*PRE*4];
__device__ float g_tu[NIMG*PRE*2];
__device__ unsigned g_mask[(size_t)NIMG*PRE*MASKW];
__device__ float g_lossC[NIMG];
__device__ float g_lossL[NIMG];

// exact-order IoU matching reference pairwise_iou (a = first operand rows)
__device__ __forceinline__ float iou_ref(float ax0,float ay0,float ax1,float ay1,
                                         float bx0,float by0,float bx1,float by1){
  float aa=__fmul_rn(__fsub_rn(ax1,ax0),__fsub_rn(ay1,ay0));
  float ab=__fmul_rn(__fsub_rn(bx1,bx0),__fsub_rn(by1,by0));
  float ltx=fmaxf(ax0,bx0), lty=fmaxf(ay0,by0);
  float rbx=fminf(ax1,bx1), rby=fminf(ay1,by1);
  float w=fmaxf(__fsub_rn(rbx,ltx),0.f), h=fmaxf(__fsub_rn(rby,lty),0.f);
  float inter=__fmul_rn(w,h);
  float denom=fmaxf(__fsub_rn(__fadd_rn(aa,ab),inter),1e-9f);
  return __fdiv_rn(inter,denom);
}

// ---------------- init: zero per-launch accumulators ----------------
__global__ void k_init(){
  int t = blockIdx.x*blockDim.x + threadIdx.x;
  if (t < 4*NIMG*256) g_hist[t] = 0u;
  if (t < NIMG*NGT)   g_bestgt[t] = 0u;
  if (t < NIMG){ g_prefix[t]=0u; g_need[t]=PRE; g_cntgt[t]=0; g_cnteq[t]=0;
                 g_lossC[t]=0.f; g_lossL[t]=0.f; }
}

// ---------------- fused mixture stats + box decode + sort keys -------------
__global__ void k_fused(const float* __restrict__ anchors, const float* __restrict__ pi,
                        const float* __restrict__ mu, const float* __restrict__ sigma,
                        const float* __restrict__ deltas){
  int t = blockIdx.x*256 + threadIdx.x;
  if (t >= NIMG*RTOT) return;
  int n = t / RTOT, r = t - n*RTOT;
  const float* pp = pi    + (size_t)n*KMIX*RTOT + r;
  const float* pm = mu    + (size_t)n*KMIX*RTOT + r;
  const float* ps = sigma + (size_t)n*KMIX*RTOT + r;
  float p[KMIX], e[KMIX], wgt[KMIX], m[KMIX], s[KMIX];
  float mx = -INFINITY;
  #pragma unroll
  for (int k=0;k<KMIX;k++){ p[k]=pp[(size_t)k*RTOT]; mx=fmaxf(mx,p[k]); }
  #pragma unroll
  for (int k=0;k<KMIX;k++) e[k]=cr_expf(__fsub_rn(p[k],mx));
  float sum=e[0];
  #pragma unroll
  for (int k=1;k<KMIX;k++) sum=__fadd_rn(sum,e[k]);
  #pragma unroll
  for (int k=0;k<KMIX;k++) wgt[k]=__fdiv_rn(e[k],sum);
  float logit=0.f;
  #pragma unroll
  for (int k=0;k<KMIX;k++){ m[k]=pm[(size_t)k*RTOT]; logit=__fadd_rn(logit,__fmul_rn(wgt[k],m[k])); }
  float epis=0.f, alea=0.f;
  #pragma unroll
  for (int k=0;k<KMIX;k++){
    float d=__fsub_rn(m[k],logit);
    epis=__fadd_rn(epis,__fmul_rn(wgt[k],__fmul_rn(d,d)));
    s[k]=ps[(size_t)k*RTOT];
    alea=__fadd_rn(alea,__fmul_rn(wgt[k],__fmul_rn(s[k],s[k])));
  }
  g_logits[t]=logit;
  g_unc[2*(size_t)t+0]=epis; g_unc[2*(size_t)t+1]=alea;
  unsigned bits = __float_as_uint(logit);
  g_keys[t] = (bits & 0x80000000u) ? ~bits : (bits | 0x80000000u);
  // apply_deltas — separate mul/add, correctly-rounded exp
  float a0=anchors[4*r+0],a1=anchors[4*r+1],a2=anchors[4*r+2],a3=anchors[4*r+3];
  float w=__fsub_rn(a2,a0), h=__fsub_rn(a3,a1);
  float cx=__fadd_rn(a0,__fmul_rn(0.5f,w)), cy=__fadd_rn(a1,__fmul_rn(0.5f,h));
  const float* d = deltas + (size_t)t*4;
  float dx=d[0],dy=d[1];
  float dw=fminf(d[2],SCALE_CLAMP),dh=fminf(d[3],SCALE_CLAMP);
  float pcx=__fadd_rn(__fmul_rn(dx,w),cx), pcy=__fadd_rn(__fmul_rn(dy,h),cy);
  float pw=__fmul_rn(cr_expf(dw),w), ph=__fmul_rn(cr_expf(dh),h);
  float* b = g_boxes + (size_t)t*4;
  b[0]=__fsub_rn(pcx,__fmul_rn(0.5f,pw)); b[1]=__fsub_rn(pcy,__fmul_rn(0.5f,ph));
  b[2]=__fadd_rn(pcx,__fmul_rn(0.5f,pw)); b[3]=__fadd_rn(pcy,__fmul_rn(0.5f,ph));
}

// ---------------- IoU vs GT pass 1: vals/argmax + best_gt ------------------
__global__ void k_iou1(const float* __restrict__ anchors, const float* __restrict__ gt){
  int n = blockIdx.x / BPI;
  int r = (blockIdx.x % BPI)*256 + threadIdx.x;
  int t = n*RTOT + r;
  __shared__ float sgt[NGT*4];
  __shared__ unsigned smax[NGT];
  if (threadIdx.x < NGT*4) sgt[threadIdx.x] = gt[n*NGT*4 + threadIdx.x];
  if (threadIdx.x < NGT) smax[threadIdx.x] = 0u;
  __syncthreads();
  float a0=anchors[4*r+0],a1=anchors[4*r+1],a2=anchors[4*r+2],a3=anchors[4*r+3];
  float best=-1.f; int bi=0;
  #pragma unroll 4
  for (int g=0; g<NGT; g++){
    float v = iou_ref(sgt[4*g+0],sgt[4*g+1],sgt[4*g+2],sgt[4*g+3], a0,a1,a2,a3);
    if (v > best){ best=v; bi=g; }
    atomicMax(&smax[g], __float_as_uint(v));   // iou >= 0 -> bit-order == float-order
  }
  g_vals[t]=best; g_gidx[t]=bi;
  __syncthreads();
  if (threadIdx.x < NGT) atomicMax(&g_bestgt[n*NGT+threadIdx.x], smax[threadIdx.x]);
}

// ---------------- IoU vs GT pass 2: low-quality match + initial labels -----
__global__ void k_iou2(const float* __restrict__ anchors, const float* __restrict__ gt){
  int n = blockIdx.x / BPI;
  int r = (blockIdx.x % BPI)*256 + threadIdx.x;
  int t = n*RTOT + r;
  __shared__ float sgt[NGT*4];
  __shared__ float sbg[NGT];
  if (threadIdx.x < NGT*4) sgt[threadIdx.x] = gt[n*NGT*4 + threadIdx.x];
  if (threadIdx.x < NGT) sbg[threadIdx.x] = __uint_as_float(g_bestgt[n*NGT+threadIdx.x]);
  __syncthreads();
  float a0=anchors[4*r+0],a1=anchors[4*r+1],a2=anchors[4*r+2],a3=anchors[4*r+3];
  bool lq=false;
  #pragma unroll 4
  for (int g=0; g<NGT; g++){
    float v = iou_ref(sgt[4*g+0],sgt[4*g+1],sgt[4*g+2],sgt[4*g+3], a0,a1,a2,a3);
    float bg = sbg[g];
    lq = lq || ((v >= __fsub_rn(bg,1e-7f)) && (bg > 0.f));
  }
  float val = g_vals[t];
  signed char lab = lq ? 1 : (val >= 0.7f ? 1 : (val >= 0.3f ? (signed char)-1 : (signed char)0));
  g_lab0[t]=lab;
}

// ---------------- radix-select top-2000 per image --------------------------
template<int L>
__global__ void k_hist(){
  __shared__ unsigned sh[256];
  int n = blockIdx.x / BPI;
  sh[threadIdx.x]=0u;
  __syncthreads();
  int t = blockIdx.x*256 + threadIdx.x;
  unsigned key = g_keys[t];
  bool ok = true;
  if (L > 0){
    unsigned pfx = g_prefix[n];
    ok = ((key ^ pfx) >> (32 - 8*L)) == 0u;
  }
  if (ok) atomicAdd(&sh[(key >> (24 - 8*L)) & 0xFFu], 1u);
  __syncthreads();
  if (sh[threadIdx.x]) atomicAdd(&g_hist[(L*NIMG+n)*256 + threadIdx.x], sh[threadIdx.x]);
}

template<int L>
__global__ void k_scanhist(){
  int n = threadIdx.x;
  if (n >= NIMG) return;
  int need = g_need[n];
  unsigned cnt=0; int b;
  for (b=255; b>0; --b){
    unsigned h = g_hist[(L*NIMG+n)*256 + b];
    if (cnt + h >= (unsigned)need) break;
    cnt += h;
  }
  g_prefix[n] |= ((unsigned)b) << (24 - 8*L);
  g_need[n] = need - (int)cnt;
}

__global__ void k_gather(){
  int n = blockIdx.x / BPI;
  int t = blockIdx.x*256 + threadIdx.x;
  int r = t - n*RTOT;
  unsigned key = g_keys[t];
  unsigned T = g_prefix[n];
  if (key > T){
    int p = atomicAdd(&g_cntgt[n], 1);
    g_sel[n*2048 + p] = (((unsigned long long)key)<<32) | (unsigned long long)(0xFFFFFFFFu - (unsigned)r);
  } else if (key == T){
    int e = atomicAdd(&g_cnteq[n], 1);
    if (e < 4096) g_eq[n*4096 + e] = r;
  }
}

__global__ void k_fineq(){
  int n = threadIdx.x;
  if (n >= NIMG) return;
  int ne = g_need[n];
  int ce = g_cnteq[n]; if (ce > 4096) ce = 4096;
  int base = g_cntgt[n];
  unsigned long long Thi = ((unsigned long long)g_prefix[n])<<32;
  for (int k=0;k<ne;k++){
    int mn=0x7fffffff, mi=-1;
    for (int j=0;j<ce;j++){ int v=g_eq[n*4096+j]; if (v<mn){mn=v;mi=j;} }
    if (mi<0) break;
    g_eq[n*4096+mi]=0x7fffffff;
    g_sel[n*2048 + base + k] = Thi | (unsigned long long)(0xFFFFFFFFu - (unsigned)mn);
  }
}

// sort 2000 composites descending -> (score desc, index asc); then gather tb/ts/tu
__global__ void k_sort(){
  __shared__ unsigned long long sa[2048];
  int n = blockIdx.x;
  for (int p=threadIdx.x;p<2048;p+=1024) sa[p] = (p<PRE) ? g_sel[n*2048+p] : 0ULL;
  __syncthreads();
  for (int k=2;k<=2048;k<<=1){
    for (int j=k>>1;j>0;j>>=1){
      for (int p=threadIdx.x;p<2048;p+=1024){
        int ixj = p ^ j;
        if (ixj > p){
          unsigned long long a=sa[p], b=sa[ixj];
          bool descBlk = ((p & k)==0);
          bool sw = descBlk ? (a < b) : (a > b);
          if (sw){ sa[p]=b; sa[ixj]=a; }
        }
      }
      __syncthreads();
    }
  }
  for (int p=threadIdx.x;p<PRE;p+=1024){
    unsigned long long c = sa[p];
    int r = (int)(0xFFFFFFFFu - (unsigned)(c & 0xFFFFFFFFull));
    g_tidx[n*PRE+p]=r;
    size_t src=(size_t)n*RTOT+r;
    g_ts[n*PRE+p]=g_logits[src];
    float b0=g_boxes[src*4+0], b1=g_boxes[src*4+1], b2=g_boxes[src*4+2], b3=g_boxes[src*4+3];
    b0=fminf(fmaxf(b0,0.f),IMGSZ); b1=fminf(fmaxf(b1,0.f),IMGSZ);
    b2=fminf(fmaxf(b2,0.f),IMGSZ); b3=fminf(fmaxf(b3,0.f),IMGSZ);
    size_t dst=(size_t)(n*PRE+p);
    g_tb[dst*4+0]=b0; g_tb[dst*4+1]=b1; g_tb[dst*4+2]=b2; g_tb[dst*4+3]=b3;
    g_tu[dst*2+0]=g_unc[src*2+0]; g_tu[dst*2+1]=g_unc[src*2+1];
  }
}

// ---------------- NMS suppression bitmask ----------------------------------
__global__ void k_mask(){
  __shared__ float stb[PRE*4];       // 32 KB
  int n  = blockIdx.x / (PRE/8);
  int i0 = (blockIdx.x % (PRE/8)) * 8;
  for (int p=threadIdx.x;p<PRE*4;p+=256) stb[p]=g_tb[(size_t)n*PRE*4+p];
  __syncthreads();
  int wi = threadIdx.x>>5, lane = threadIdx.x&31;
  int i = i0 + wi;
  float x0=stb[4*i+0],y0=stb[4*i+1],x1=stb[4*i+2],y1=stb[4*i+3];
  for (int w=0;w<MASKW;w++){
    int j=w*32+lane;
    bool pr=false;
    if (j<PRE && j>i){
      pr = iou_ref(x0,y0,x1,y1, stb[4*j+0],stb[4*j+1],stb[4*j+2],stb[4*j+3]) > NMS_T;
    }
    unsigned bits=__ballot_sync(0xFFFFFFFFu,pr);
    if (lane==0) g_mask[((size_t)(n*PRE+i))*MASKW + w]=bits;
  }
}

// ---------------- greedy NMS + final selection + output write --------------
__global__ void k_greedy(float* __restrict__ out){
  int n = blockIdx.x;
  volatile __shared__ unsigned removed[MASKW];
  __shared__ unsigned char skeep[PRE];
  __shared__ int soidx[POST];
  __shared__ unsigned char sokept[POST];
  int tid=threadIdx.x;
  int g = tid>>6, lane = tid&63;           // 16 groups x 64 lanes
  if (tid < MASKW) removed[tid]=0u;
  unsigned cur=0u;
  if (lane < MASKW) cur = g_mask[((size_t)(n*PRE+g))*MASKW + lane];
  __syncthreads();
  for (int i=0;i<PRE;++i){
    unsigned rw = removed[i>>5];
    bool rem = (rw >> (i&31)) & 1u;
    if (!rem && (i&15)==g && lane<MASKW) removed[lane] = removed[lane] | cur;
    __syncthreads();
    if ((i&15)==g){
      int nr = i+16;
      cur = (nr<PRE && lane<MASKW) ? g_mask[((size_t)(n*PRE+nr))*MASKW + lane] : 0u;
    }
  }
  __syncthreads();
  for (int i=tid;i<PRE;i+=1024){
    size_t b=(size_t)(n*PRE+i)*4;
    float w = __fsub_rn(g_tb[b+2],g_tb[b+0]);
    float h = __fsub_rn(g_tb[b+3],g_tb[b+1]);
    bool k = !((removed[i>>5]>>(i&31))&1u) && (w>0.f) && (h>0.f);
    skeep[i] = k ? 1 : 0;
  }
  __syncthreads();
  if (tid==0){
    int c=0;
    for (int i=0;i<PRE && c<POST;i++) if (skeep[i]){ soidx[c]=i; sokept[c]=1; c++; }
    for (int i=0;i<PRE && c<POST;i++) if (!skeep[i]){ soidx[c]=i; sokept[c]=0; c++; }
  }
  __syncthreads();
  const float NEGINF = __int_as_float(0xff800000);
  for (int o=tid;o<POST;o+=1024){
    int i=soidx[o];
    size_t src=(size_t)(n*PRE+i);
    float* pb = out + ((size_t)n*POST+o)*4;
    pb[0]=g_tb[src*4+0]; pb[1]=g_tb[src*4+1]; pb[2]=g_tb[src*4+2]; pb[3]=g_tb[src*4+3];
    out[(size_t)NIMG*POST*4 + (size_t)n*POST + o] = sokept[o] ? g_ts[src] : NEGINF;
    out[(size_t)NIMG*POST*5 + ((size_t)n*POST+o)*2 + 0] = g_tu[src*2+0];
    out[(size_t)NIMG*POST*5 + ((size_t)n*POST+o)*2 + 1] = g_tu[src*2+1];
  }
}

// ---------------- label sampling (sequential cumsum) + losses --------------
__global__ void k_loss(const float* __restrict__ anchors, const float* __restrict__ pi,
                       const float* __restrict__ mu, const float* __restrict__ sigma,
                       const float* __restrict__ deltas, const float* __restrict__ gt){
  int n = blockIdx.x;
  int tid = threadIdx.x;              // 256 threads
  int lane = tid & 31, wid = tid >> 5;
  __shared__ float sgt[NGT*4];
  __shared__ int wsum[8];
  __shared__ int wp[8], wn[8];
  __shared__ int s_npos;
  __shared__ float sred[256];
  if (tid < NGT*4) sgt[tid] = gt[n*NGT*4 + tid];
  // phase 1: total positives
  int cnt=0;
  for (int base=0;base<RTOT;base+=256){
    cnt += (g_lab0[(size_t)n*RTOT + base + tid]==1) ? 1 : 0;
  }
  #pragma unroll
  for (int off=16;off;off>>=1) cnt += __shfl_down_sync(0xFFFFFFFFu,cnt,off);
  if (lane==0) wsum[wid]=cnt;
  __syncthreads();
  if (tid==0){
    int tot=0;
    for (int w=0;w<8;w++) tot+=wsum[w];
    s_npos = tot<128 ? tot : 128;
  }
  __syncthreads();
  int npos = s_npos;
  int nquota = 256 - npos;
  int carry_p=0, carry_n=0;
  float accC=0.f, accL=0.f;
  unsigned lmask_le = 0xFFFFFFFFu >> (31-lane);
  for (int base=0;base<RTOT;base+=256){
    int r = base + tid;
    signed char lb = g_lab0[(size_t)n*RTOT + r];
    bool pf = (lb==1), nf = (lb==0);
    unsigned bp=__ballot_sync(0xFFFFFFFFu,pf), bn=__ballot_sync(0xFFFFFFFFu,nf);
    if (lane==0){ wp[wid]=__popc(bp); wn[wid]=__popc(bn); }
    __syncthreads();
    int offp=0, offn=0, totp=0, totn=0;
    for (int w=0;w<8;w++){
      if (w<wid){ offp+=wp[w]; offn+=wn[w]; }
      totp+=wp[w]; totn+=wn[w];
    }
    int cump = carry_p + offp + __popc(bp & lmask_le);
    int cumn = carry_n + offn + __popc(bn & lmask_le);
    bool keep_p = pf && (cump <= npos);
    bool keep_n = nf && (cumn <= nquota);
    if (keep_p || keep_n){
      // MDN NLL for this anchor, matching JAX log_softmax + logsumexp
      float t = fminf(fmaxf(g_vals[(size_t)n*RTOT+r],0.f),1.f);
      const float* pp = pi    + (size_t)n*KMIX*RTOT + r;
      const float* pm = mu    + (size_t)n*KMIX*RTOT + r;
      const float* ps = sigma + (size_t)n*KMIX*RTOT + r;
      float pv[KMIX], sh[KMIX], comp[KMIX];
      float mx=-INFINITY;
      #pragma unroll
      for (int k=0;k<KMIX;k++){ pv[k]=pp[(size_t)k*RTOT]; mx=fmaxf(mx,pv[k]); }
      #pragma unroll
      for (int k=0;k<KMIX;k++) sh[k]=__fsub_rn(pv[k],mx);
      float se=cr_expf(sh[0]);
      #pragma unroll
      for (int k=1;k<KMIX;k++) se=__fadd_rn(se,cr_expf(sh[k]));
      float logse = cr_logf(se);
      float cmax=-INFINITY;
      #pragma unroll
      for (int k=0;k<KMIX;k++){
        float mv=pm[(size_t)k*RTOT], sv=ps[(size_t)k*RTOT];
        float lp=__fsub_rn(sh[k],logse);
        float z=__fdiv_rn(__fsub_rn(t,mv),sv);
        float c=__fsub_rn(__fsub_rn(__fsub_rn(lp,__fmul_rn(0.5f,__fmul_rn(z,z))),cr_logf(sv)),HALF_LOG2PI);
        comp[k]=c;
        cmax=fmaxf(cmax,c);
      }
      float s2=cr_expf(__fsub_rn(comp[0],cmax));
      #pragma unroll
      for (int k=1;k<KMIX;k++) s2=__fadd_rn(s2,cr_expf(__fsub_rn(comp[k],cmax)));
      accC += -(__fadd_rn(cmax,cr_logf(s2)));
    }
    if (keep_p){
      int gi = g_gidx[(size_t)n*RTOT+r];
      float t0=sgt[4*gi+0],t1=sgt[4*gi+1],t2=sgt[4*gi+2],t3=sgt[4*gi+3];
      float a0=anchors[4*r+0],a1=anchors[4*r+1],a2=anchors[4*r+2],a3=anchors[4*r+3];
      float sw=__fsub_rn(a2,a0), sh2=__fsub_rn(a3,a1);
      float scx=__fadd_rn(a0,__fmul_rn(0.5f,sw)), scy=__fadd_rn(a1,__fmul_rn(0.5f,sh2));
      float tw=__fsub_rn(t2,t0), th=__fsub_rn(t3,t1);
      float tcx=__fadd_rn(t0,__fmul_rn(0.5f,tw)), tcy=__fadd_rn(t1,__fmul_rn(0.5f,th));
      float gd0=__fdiv_rn(__fsub_rn(tcx,scx),sw), gd1=__fdiv_rn(__fsub_rn(tcy,scy),sh2);
      float gd2=cr_logf(__fdiv_rn(tw,sw)), gd3=cr_logf(__fdiv_rn(th,sh2));
      const float* dd = deltas + ((size_t)n*RTOT + r)*4;
      accL += fabsf(__fsub_rn(dd[0],gd0))+fabsf(__fsub_rn(dd[1],gd1))
            + fabsf(__fsub_rn(dd[2],gd2))+fabsf(__fsub_rn(dd[3],gd3));
    }
    carry_p += totp; carry_n += totn;
    __syncthreads();
    if (carry_p >= npos && carry_n >= nquota) break;
  }
  // block reduce accC, accL -> per-image partials (deterministic)
  sred[tid]=accC; __syncthreads();
  for (int s=128;s;s>>=1){ if (tid<s) sred[tid]+=sred[tid+s]; __syncthreads(); }
  if (tid==0) g_lossC[n] = sred[0];
  __syncthreads();
  sred[tid]=accL; __syncthreads();
  for (int s=128;s;s>>=1){ if (tid<s) sred[tid]+=sred[tid+s]; __syncthreads(); }
  if (tid==0) g_lossL[n] = sred[0];
}

__global__ void k_wloss(float* __restrict__ out){
  if (threadIdx.x==0){
    float c=0.f,l=0.f;
    for (int n=0;n<NIMG;n++){ c+=g_lossC[n]; l+=g_lossL[n]; }
    out[(size_t)NIMG*POST*7 + 0] = c / 2048.f;
    out[(size_t)NIMG*POST*7 + 1] = l / 2048.f;
  }
}

// ---------------- launch -----------------------------------------------------
extern "C" void kernel_launch(void* const* d_in, const int* in_sizes, int n_in,
                              void* d_out, int out_size){
  const float* anchors = (const float*)d_in[0];
  const float* pi      = (const float*)d_in[1];
  const float* mu      = (const float*)d_in[2];
  const float* sigma   = (const float*)d_in[3];
  const float* deltas  = (const float*)d_in[4];
  const float* gt      = (const float*)d_in[5];
  float* out = (float*)d_out;
  (void)in_sizes; (void)n_in; (void)out_size;

  k_init<<<8,1024>>>();
  k_fused<<<NIMG*BPI,256>>>(anchors,pi,mu,sigma,deltas);
  k_iou1<<<NIMG*BPI,256>>>(anchors,gt);
  k_iou2<<<NIMG*BPI,256>>>(anchors,gt);
  k_hist<0><<<NIMG*BPI,256>>>();  k_scanhist<0><<<1,32>>>();
  k_hist<1><<<NIMG*BPI,256>>>();  k_scanhist<1><<<1,32>>>();
  k_hist<2><<<NIMG*BPI,256>>>();  k_scanhist<2><<<1,32>>>();
  k_hist<3><<<NIMG*BPI,256>>>();  k_scanhist<3><<<1,32>>>();
  k_gather<<<NIMG*BPI,256>>>();
  k_fineq<<<1,32>>>();
  k_sort<<<NIMG,1024>>>();
  k_mask<<<NIMG*(PRE/8),256>>>();
  k_greedy<<<NIMG,1024>>>(out);
  k_loss<<<NIMG,256>>>(anchors,pi,mu,sigma,deltas,gt);
  k_wloss<<<1,32>>>(out);
}

// round 5
// speedup vs baseline: 1.7306x; 1.7306x over previous
#include <cuda_runtime.h>
#include <math.h>
#include <stdint.h>

#define NIMG 8
#define KMIX 5
#define RTOT 96000
#define NGT 32
#define PRE 2000
#define POST 1000
#define MASKW 63
#define BPI (RTOT/256)
#define IMGSZ 1280.0f
#define SCALE_CLAMP 4.135166556742356f
#define HALF_LOG2PI 0.9189385332046727f
#define NMS_T 0.7f

__device__ __forceinline__ float cr_expf(float x){ return (float)exp((double)x); }
__device__ __forceinline__ float cr_logf(float x){ return (float)log((double)x); }

// fast near-correctly-rounded float exp via short double poly (deg-11 Taylor, err ~2^-46)
__device__ __forceinline__ float fexp(float xf){
  if (xf < -80.f || xf > 80.f) return cr_expf(xf);
  double x = (double)xf;
  double kd = rint(x * 1.4426950408889634);
  double r = fma(-kd, 0.6931471805599453, x);
  r = fma(-kd, 2.3190468138462996e-17, r);
  double p = 2.505210838544172e-08;
  p = fma(p, r, 2.755731922398589e-07);
  p = fma(p, r, 2.755731922398589e-06);
  p = fma(p, r, 2.480158730158730e-05);
  p = fma(p, r, 1.984126984126984e-04);
  p = fma(p, r, 1.388888888888889e-03);
  p = fma(p, r, 8.333333333333333e-03);
  p = fma(p, r, 4.166666666666666e-02);
  p = fma(p, r, 1.666666666666667e-01);
  p = fma(p, r, 0.5);
  p = fma(p, r, 1.0);
  p = fma(p, r, 1.0);
  int ki = (int)kd;
  double sc = __hiloint2double((1023 + ki) << 20, 0);
  return (float)(p * sc);
}

// ---------------- static device scratch ----------------
__device__ float g_logits[NIMG*RTOT];
__device__ unsigned g_keys[NIMG*RTOT];
__device__ float g_vals[NIMG*RTOT];
__device__ int   g_gidx[NIMG*RTOT];
__device__ unsigned g_bestgt[NIMG*NGT];
__device__ signed char g_lab0[NIMG*RTOT];
__device__ unsigned g_hist[4*NIMG*256];
__device__ unsigned g_prefix[NIMG];
__device__ int g_need[NIMG];
__device__ int g_cntgt[NIMG];
__device__ int g_cnteq[NIMG];
__device__ unsigned long long g_sel[NIMG*2048];
__device__ int g_eq[NIMG*4096];
__device__ float g_ts[NIMG*PRE];
__device__ float g_tb[NIMG*PRE*4];
__device__ float g_tu[NIMG*PRE*2];
__device__ unsigned g_mask[(size_t)NIMG*PRE*MASKW];   // zero-init; lower-tri words never written
__device__ float g_lossC[NIMG];
__device__ float g_lossL[NIMG];

__device__ __forceinline__ float iou_ref(float ax0,float ay0,float ax1,float ay1,
                                         float bx0,float by0,float bx1,float by1){
  float aa=__fmul_rn(__fsub_rn(ax1,ax0),__fsub_rn(ay1,ay0));
  float ab=__fmul_rn(__fsub_rn(bx1,bx0),__fsub_rn(by1,by0));
  float ltx=fmaxf(ax0,bx0), lty=fmaxf(ay0,by0);
  float rbx=fminf(ax1,bx1), rby=fminf(ay1,by1);
  float w=fmaxf(__fsub_rn(rbx,ltx),0.f), h=fmaxf(__fsub_rn(rby,lty),0.f);
  float inter=__fmul_rn(w,h);
  float denom=fmaxf(__fsub_rn(__fadd_rn(aa,ab),inter),1e-9f);
  return __fdiv_rn(inter,denom);
}

__global__ void k_init(){
  int t = blockIdx.x*blockDim.x + threadIdx.x;
  if (t < 4*NIMG*256) g_hist[t] = 0u;
  if (t < NIMG*NGT)   g_bestgt[t] = 0u;
  if (t < NIMG){ g_prefix[t]=0u; g_need[t]=PRE; g_cntgt[t]=0; g_cnteq[t]=0; }
}

// slim fused: logits + radix keys only
__global__ void k_fused(const float* __restrict__ pi, const float* __restrict__ mu){
  int t = blockIdx.x*256 + threadIdx.x;
  int n = t / RTOT, r = t - n*RTOT;
  const float* pp = pi + (size_t)n*KMIX*RTOT + r;
  const float* pm = mu + (size_t)n*KMIX*RTOT + r;
  float p[KMIX], e[KMIX];
  float mx = -INFINITY;
  #pragma unroll
  for (int k=0;k<KMIX;k++){ p[k]=pp[(size_t)k*RTOT]; mx=fmaxf(mx,p[k]); }
  #pragma unroll
  for (int k=0;k<KMIX;k++) e[k]=fexp(__fsub_rn(p[k],mx));
  float sum=e[0];
  #pragma unroll
  for (int k=1;k<KMIX;k++) sum=__fadd_rn(sum,e[k]);
  float logit=0.f;
  #pragma unroll
  for (int k=0;k<KMIX;k++)
    logit=__fadd_rn(logit,__fmul_rn(__fdiv_rn(e[k],sum),pm[(size_t)k*RTOT]));
  g_logits[t]=logit;
  unsigned bits = __float_as_uint(logit);
  g_keys[t] = (bits & 0x80000000u) ? ~bits : (bits | 0x80000000u);
}

__global__ void k_iou1(const float* __restrict__ anchors, const float* __restrict__ gt){
  int n = blockIdx.x / BPI;
  int r = (blockIdx.x % BPI)*256 + threadIdx.x;
  int t = n*RTOT + r;
  __shared__ float sgt[NGT*4];
  __shared__ unsigned smax[NGT];
  if (threadIdx.x < NGT*4) sgt[threadIdx.x] = gt[n*NGT*4 + threadIdx.x];
  if (threadIdx.x < NGT) smax[threadIdx.x] = 0u;
  __syncthreads();
  float a0=anchors[4*r+0],a1=anchors[4*r+1],a2=anchors[4*r+2],a3=anchors[4*r+3];
  float best=-1.f; int bi=0;
  #pragma unroll 4
  for (int g=0; g<NGT; g++){
    float v = iou_ref(sgt[4*g+0],sgt[4*g+1],sgt[4*g+2],sgt[4*g+3], a0,a1,a2,a3);
    if (v > best){ best=v; bi=g; }
    atomicMax(&smax[g], __float_as_uint(v));
  }
  g_vals[t]=best; g_gidx[t]=bi;
  __syncthreads();
  if (threadIdx.x < NGT) atomicMax(&g_bestgt[n*NGT+threadIdx.x], smax[threadIdx.x]);
}

__global__ void k_iou2(const float* __restrict__ anchors, const float* __restrict__ gt){
  int n = blockIdx.x / BPI;
  int r = (blockIdx.x % BPI)*256 + threadIdx.x;
  int t = n*RTOT + r;
  __shared__ float sgt[NGT*4];
  __shared__ float sbg[NGT];
  if (threadIdx.x < NGT*4) sgt[threadIdx.x] = gt[n*NGT*4 + threadIdx.x];
  if (threadIdx.x < NGT) sbg[threadIdx.x] = __uint_as_float(g_bestgt[n*NGT+threadIdx.x]);
  __syncthreads();
  float a0=anchors[4*r+0],a1=anchors[4*r+1],a2=anchors[4*r+2],a3=anchors[4*r+3];
  bool lq=false;
  #pragma unroll 4
  for (int g=0; g<NGT; g++){
    float v = iou_ref(sgt[4*g+0],sgt[4*g+1],sgt[4*g+2],sgt[4*g+3], a0,a1,a2,a3);
    float bg = sbg[g];
    lq = lq || ((v >= __fsub_rn(bg,1e-7f)) && (bg > 0.f));
  }
  float val = g_vals[t];
  signed char lab = lq ? 1 : (val >= 0.7f ? 1 : (val >= 0.3f ? (signed char)-1 : (signed char)0));
  g_lab0[t]=lab;
}

template<int L>
__global__ void k_hist(){
  __shared__ unsigned sh[256];
  int n = blockIdx.x / BPI;
  sh[threadIdx.x]=0u;
  __syncthreads();
  int t = blockIdx.x*256 + threadIdx.x;
  unsigned key = g_keys[t];
  bool ok = true;
  if (L > 0) ok = ((key ^ g_prefix[n]) >> (32 - 8*L)) == 0u;
  if (ok) atomicAdd(&sh[(key >> (24 - 8*L)) & 0xFFu], 1u);
  __syncthreads();
  if (sh[threadIdx.x]) atomicAdd(&g_hist[(L*NIMG+n)*256 + threadIdx.x], sh[threadIdx.x]);
}

template<int L>
__global__ void k_scanhist(){
  int n = threadIdx.x;
  if (n >= NIMG) return;
  int need = g_need[n];
  unsigned cnt=0; int b;
  for (b=255; b>0; --b){
    unsigned h = g_hist[(L*NIMG+n)*256 + b];
    if (cnt + h >= (unsigned)need) break;
    cnt += h;
  }
  g_prefix[n] |= ((unsigned)b) << (24 - 8*L);
  g_need[n] = need - (int)cnt;
}

__global__ void k_gather(){
  int n = blockIdx.x / BPI;
  int t = blockIdx.x*256 + threadIdx.x;
  int r = t - n*RTOT;
  unsigned key = g_keys[t];
  unsigned T = g_prefix[n];
  if (key > T){
    int p = atomicAdd(&g_cntgt[n], 1);
    g_sel[n*2048 + p] = (((unsigned long long)key)<<32) | (unsigned long long)(0xFFFFFFFFu - (unsigned)r);
  } else if (key == T){
    int e = atomicAdd(&g_cnteq[n], 1);
    if (e < 4096) g_eq[n*4096 + e] = r;
  }
}

__global__ void k_fineq(){
  int n = threadIdx.x;
  if (n >= NIMG) return;
  int ne = g_need[n];
  int ce = g_cnteq[n]; if (ce > 4096) ce = 4096;
  int base = g_cntgt[n];
  unsigned long long Thi = ((unsigned long long)g_prefix[n])<<32;
  for (int k=0;k<ne;k++){
    int mn=0x7fffffff, mi=-1;
    for (int j=0;j<ce;j++){ int v=g_eq[n*4096+j]; if (v<mn){mn=v;mi=j;} }
    if (mi<0) break;
    g_eq[n*4096+mi]=0x7fffffff;
    g_sel[n*2048 + base + k] = Thi | (unsigned long long)(0xFFFFFFFFu - (unsigned)mn);
  }
}

// bitonic sort + deferred unc/box decode for selected 2000
__global__ void k_sort(const float* __restrict__ anchors, const float* __restrict__ pi,
                       const float* __restrict__ mu, const float* __restrict__ sigma,
                       const float* __restrict__ deltas){
  __shared__ unsigned long long sa[2048];
  int n = blockIdx.x;
  for (int p=threadIdx.x;p<2048;p+=1024) sa[p] = (p<PRE) ? g_sel[n*2048+p] : 0ULL;
  __syncthreads();
  for (int k=2;k<=2048;k<<=1){
    for (int j=k>>1;j>0;j>>=1){
      for (int p=threadIdx.x;p<2048;p+=1024){
        int ixj = p ^ j;
        if (ixj > p){
          unsigned long long a=sa[p], b=sa[ixj];
          bool sw = ((p & k)==0) ? (a < b) : (a > b);
          if (sw){ sa[p]=b; sa[ixj]=a; }
        }
      }
      __syncthreads();
    }
  }
  for (int p=threadIdx.x;p<PRE;p+=1024){
    unsigned long long c = sa[p];
    int r = (int)(0xFFFFFFFFu - (unsigned)(c & 0xFFFFFFFFull));
    size_t src=(size_t)n*RTOT+r;
    float lg = g_logits[src];
    g_ts[n*PRE+p]=lg;
    const float* pp = pi    + (size_t)n*KMIX*RTOT + r;
    const float* pm = mu    + (size_t)n*KMIX*RTOT + r;
    const float* ps = sigma + (size_t)n*KMIX*RTOT + r;
    float pv[KMIX], e[KMIX];
    float mx=-INFINITY;
    #pragma unroll
    for (int k=0;k<KMIX;k++){ pv[k]=pp[(size_t)k*RTOT]; mx=fmaxf(mx,pv[k]); }
    #pragma unroll
    for (int k=0;k<KMIX;k++) e[k]=fexp(__fsub_rn(pv[k],mx));
    float sum=e[0];
    #pragma unroll
    for (int k=1;k<KMIX;k++) sum=__fadd_rn(sum,e[k]);
    float epis=0.f, alea=0.f;
    #pragma unroll
    for (int k=0;k<KMIX;k++){
      float w=__fdiv_rn(e[k],sum);
      float mv=pm[(size_t)k*RTOT], sv=ps[(size_t)k*RTOT];
      float d=__fsub_rn(mv,lg);
      epis=__fadd_rn(epis,__fmul_rn(w,__fmul_rn(d,d)));
      alea=__fadd_rn(alea,__fmul_rn(w,__fmul_rn(sv,sv)));
    }
    size_t dst=(size_t)(n*PRE+p);
    g_tu[dst*2+0]=epis; g_tu[dst*2+1]=alea;
    float a0=anchors[4*r+0],a1=anchors[4*r+1],a2=anchors[4*r+2],a3=anchors[4*r+3];
    float w=__fsub_rn(a2,a0), h=__fsub_rn(a3,a1);
    float cx=__fadd_rn(a0,__fmul_rn(0.5f,w)), cy=__fadd_rn(a1,__fmul_rn(0.5f,h));
    const float* d = deltas + src*4;
    float dw=fminf(d[2],SCALE_CLAMP),dh=fminf(d[3],SCALE_CLAMP);
    float pcx=__fadd_rn(__fmul_rn(d[0],w),cx), pcy=__fadd_rn(__fmul_rn(d[1],h),cy);
    float pw=__fmul_rn(cr_expf(dw),w), ph=__fmul_rn(cr_expf(dh),h);
    float b0=__fsub_rn(pcx,__fmul_rn(0.5f,pw)), b1=__fsub_rn(pcy,__fmul_rn(0.5f,ph));
    float b2=__fadd_rn(pcx,__fmul_rn(0.5f,pw)), b3=__fadd_rn(pcy,__fmul_rn(0.5f,ph));
    b0=fminf(fmaxf(b0,0.f),IMGSZ); b1=fminf(fmaxf(b1,0.f),IMGSZ);
    b2=fminf(fmaxf(b2,0.f),IMGSZ); b3=fminf(fmaxf(b3,0.f),IMGSZ);
    g_tb[dst*4+0]=b0; g_tb[dst*4+1]=b1; g_tb[dst*4+2]=b2; g_tb[dst*4+3]=b3;
  }
}

// upper-triangle suppression mask (lower words stay zero-initialized)
__global__ void k_mask(){
  __shared__ float stb[PRE*4];
  int n  = blockIdx.x / (PRE/8);
  int i0 = (blockIdx.x % (PRE/8)) * 8;
  for (int p=threadIdx.x;p<PRE*4;p+=256) stb[p]=g_tb[(size_t)n*PRE*4+p];
  __syncthreads();
  int wi = threadIdx.x>>5, lane = threadIdx.x&31;
  int i = i0 + wi;
  float x0=stb[4*i+0],y0=stb[4*i+1],x1=stb[4*i+2],y1=stb[4*i+3];
  for (int w=i>>5; w<MASKW; w++){
    int j=w*32+lane;
    bool pr=false;
    if (j<PRE && j>i)
      pr = iou_ref(x0,y0,x1,y1, stb[4*j+0],stb[4*j+1],stb[4*j+2],stb[4*j+3]) > NMS_T;
    unsigned bits=__ballot_sync(0xFFFFFFFFu,pr);
    if (lane==0) g_mask[((size_t)(n*PRE+i))*MASKW + w]=bits;
  }
}

// greedy NMS: warp-register scan, no barriers in the chain
__global__ void k_greedy(float* __restrict__ out){
  int n = blockIdx.x;
  int tid = threadIdx.x;                 // 1024
  __shared__ unsigned srem[64];
  __shared__ unsigned skw[63];
  __shared__ int spre[64];
  if (tid < 32){
    int lane = tid;
    bool l1 = (lane + 32) < MASKW;       // lanes 0..30
    unsigned rem0=0u, rem1=0u;
    unsigned pf0[16], pf1[16];
    const unsigned* M = g_mask + (size_t)n*PRE*MASKW;
    #pragma unroll
    for (int d=0; d<16; ++d){
      pf0[d] = M[(size_t)d*MASKW + lane];
      pf1[d] = l1 ? M[(size_t)d*MASKW + lane + 32] : 0u;
    }
    for (int i=0; i<PRE; i+=16){
      #pragma unroll
      for (int d=0; d<16; ++d){
        int idx = i + d;
        int w = idx >> 5;
        unsigned wa = __shfl_sync(0xFFFFFFFFu, rem0, w & 31);
        unsigned wb = __shfl_sync(0xFFFFFFFFu, rem1, w & 31);
        unsigned word = (w < 32) ? wa : wb;
        if (!((word >> (idx & 31)) & 1u)){ rem0 |= pf0[d]; rem1 |= pf1[d]; }
        int nr = idx + 16;
        if (nr < PRE){
          pf0[d] = M[(size_t)nr*MASKW + lane];
          pf1[d] = l1 ? M[(size_t)nr*MASKW + lane + 32] : 0u;
        } else { pf0[d]=0u; pf1[d]=0u; }
      }
    }
    srem[lane] = rem0;
    srem[lane+32] = l1 ? rem1 : 0u;
  }
  __syncthreads();
  for (int base=0; base<2048; base+=1024){
    int idx = base + tid;
    int w = idx >> 5;
    bool keep = false;
    if (idx < PRE){
      size_t b=(size_t)(n*PRE+idx)*4;
      float bw=__fsub_rn(g_tb[b+2],g_tb[b+0]);
      float bh=__fsub_rn(g_tb[b+3],g_tb[b+1]);
      keep = !((srem[w]>>(idx&31))&1u) && (bw>0.f) && (bh>0.f);
    }
    unsigned bal=__ballot_sync(0xFFFFFFFFu, keep);
    if ((idx&31)==0 && w<MASKW) skw[w]=bal;
  }
  __syncthreads();
  if (tid==0){ int run=0; for(int q=0;q<MASKW;q++){ spre[q]=run; run+=__popc(skw[q]); } spre[63]=run; }
  __syncthreads();
  int K = spre[63];
  const float NEGINF = __int_as_float(0xff800000);
  for (int base=0; base<2048; base+=1024){
    int idx = base + tid;
    if (idx >= PRE) continue;
    int w = idx>>5, b = idx&31;
    unsigned kwv = skw[w];
    bool kept = (kwv>>b)&1u;
    int kb = spre[w] + __popc(kwv & ((1u<<b)-1u));
    int pos = kept ? kb : (K + (idx - kb));
    if (pos < POST){
      size_t src = (size_t)(n*PRE+idx);
      float* pb = out + ((size_t)n*POST+pos)*4;
      pb[0]=g_tb[src*4+0]; pb[1]=g_tb[src*4+1]; pb[2]=g_tb[src*4+2]; pb[3]=g_tb[src*4+3];
      out[(size_t)NIMG*POST*4 + (size_t)n*POST + pos] = kept ? g_ts[src] : NEGINF;
      out[(size_t)NIMG*POST*5 + ((size_t)n*POST+pos)*2 + 0] = g_tu[src*2+0];
      out[(size_t)NIMG*POST*5 + ((size_t)n*POST+pos)*2 + 1] = g_tu[src*2+1];
    }
  }
}

__global__ void k_loss(const float* __restrict__ anchors, const float* __restrict__ pi,
                       const float* __restrict__ mu, const float* __restrict__ sigma,
                       const float* __restrict__ deltas, const float* __restrict__ gt){
  int n = blockIdx.x;
  int tid = threadIdx.x;               // 1024
  int lane = tid & 31, wid = tid >> 5; // 32 warps
  __shared__ float sgt[NGT*4];
  __shared__ int wsum[32], wp[32], wn[32];
  __shared__ int s_npos;
  __shared__ float sred[1024];
  if (tid < NGT*4) sgt[tid] = gt[n*NGT*4 + tid];
  int cnt=0;
  for (int base=0;base<RTOT;base+=1024){
    int r = base + tid;
    if (r < RTOT) cnt += (g_lab0[(size_t)n*RTOT + r]==1) ? 1 : 0;
  }
  #pragma unroll
  for (int off=16;off;off>>=1) cnt += __shfl_down_sync(0xFFFFFFFFu,cnt,off);
  if (lane==0) wsum[wid]=cnt;
  __syncthreads();
  if (tid==0){ int tot=0; for (int w=0;w<32;w++) tot+=wsum[w]; s_npos = tot<128 ? tot : 128; }
  __syncthreads();
  int npos = s_npos;
  int nquota = 256 - npos;
  int carry_p=0, carry_n=0;
  float accC=0.f, accL=0.f;
  unsigned lmask_le = 0xFFFFFFFFu >> (31-lane);
  for (int base=0;base<RTOT;base+=1024){
    int r = base + tid;
    signed char lb = (r < RTOT) ? g_lab0[(size_t)n*RTOT + r] : (signed char)-1;
    bool pf = (lb==1), nf = (lb==0);
    unsigned bp=__ballot_sync(0xFFFFFFFFu,pf), bn=__ballot_sync(0xFFFFFFFFu,nf);
    if (lane==0){ wp[wid]=__popc(bp); wn[wid]=__popc(bn); }
    __syncthreads();
    int offp=0, offn=0, totp=0, totn=0;
    for (int w=0;w<32;w++){
      if (w<wid){ offp+=wp[w]; offn+=wn[w]; }
      totp+=wp[w]; totn+=wn[w];
    }
    int cump = carry_p + offp + __popc(bp & lmask_le);
    int cumn = carry_n + offn + __popc(bn & lmask_le);
    bool keep_p = pf && (cump <= npos);
    bool keep_n = nf && (cumn <= nquota);
    if (keep_p || keep_n){
      float t = fminf(fmaxf(g_vals[(size_t)n*RTOT+r],0.f),1.f);
      const float* pp = pi    + (size_t)n*KMIX*RTOT + r;
      const float* pm = mu    + (size_t)n*KMIX*RTOT + r;
      const float* ps = sigma + (size_t)n*KMIX*RTOT + r;
      float pv[KMIX], sh[KMIX], comp[KMIX];
      float mx=-INFINITY;
      #pragma unroll
      for (int k=0;k<KMIX;k++){ pv[k]=pp[(size_t)k*RTOT]; mx=fmaxf(mx,pv[k]); }
      #pragma unroll
      for (int k=0;k<KMIX;k++) sh[k]=__fsub_rn(pv[k],mx);
      float se=cr_expf(sh[0]);
      #pragma unroll
      for (int k=1;k<KMIX;k++) se=__fadd_rn(se,cr_expf(sh[k]));
      float logse = cr_logf(se);
      float cmax=-INFINITY;
      #pragma unroll
      for (int k=0;k<KMIX;k++){
        float mv=pm[(size_t)k*RTOT], sv=ps[(size_t)k*RTOT];
        float lp=__fsub_rn(sh[k],logse);
        float z=__fdiv_rn(__fsub_rn(t,mv),sv);
        float c=__fsub_rn(__fsub_rn(__fsub_rn(lp,__fmul_rn(0.5f,__fmul_rn(z,z))),cr_logf(sv)),HALF_LOG2PI);
        comp[k]=c; cmax=fmaxf(cmax,c);
      }
      float s2=cr_expf(__fsub_rn(comp[0],cmax));
      #pragma unroll
      for (int k=1;k<KMIX;k++) s2=__fadd_rn(s2,cr_expf(__fsub_rn(comp[k],cmax)));
      accC += -(__fadd_rn(cmax,cr_logf(s2)));
    }
    if (keep_p){
      int gi = g_gidx[(size_t)n*RTOT+r];
      float t0=sgt[4*gi+0],t1=sgt[4*gi+1],t2=sgt[4*gi+2],t3=sgt[4*gi+3];
      float a0=anchors[4*r+0],a1=anchors[4*r+1],a2=anchors[4*r+2],a3=anchors[4*r+3];
      float sw=__fsub_rn(a2,a0), sh2=__fsub_rn(a3,a1);
      float scx=__fadd_rn(a0,__fmul_rn(0.5f,sw)), scy=__fadd_rn(a1,__fmul_rn(0.5f,sh2));
      float tw=__fsub_rn(t2,t0), th=__fsub_rn(t3,t1);
      float tcx=__fadd_rn(t0,__fmul_rn(0.5f,tw)), tcy=__fadd_rn(t1,__fmul_rn(0.5f,th));
      float gd0=__fdiv_rn(__fsub_rn(tcx,scx),sw), gd1=__fdiv_rn(__fsub_rn(tcy,scy),sh2);
      float gd2=cr_logf(__fdiv_rn(tw,sw)), gd3=cr_logf(__fdiv_rn(th,sh2));
      const float* dd = deltas + ((size_t)n*RTOT + r)*4;
      accL += fabsf(__fsub_rn(dd[0],gd0))+fabsf(__fsub_rn(dd[1],gd1))
            + fabsf(__fsub_rn(dd[2],gd2))+fabsf(__fsub_rn(dd[3],gd3));
    }
    carry_p += totp; carry_n += totn;
    __syncthreads();
    if (carry_p >= npos && carry_n >= nquota) break;
  }
  sred[tid]=accC; __syncthreads();
  for (int s=512;s;s>>=1){ if (tid<s) sred[tid]+=sred[tid+s]; __syncthreads(); }
  if (tid==0) g_lossC[n] = sred[0];
  __syncthreads();
  sred[tid]=accL; __syncthreads();
  for (int s=512;s;s>>=1){ if (tid<s) sred[tid]+=sred[tid+s]; __syncthreads(); }
  if (tid==0) g_lossL[n] = sred[0];
}

__global__ void k_wloss(float* __restrict__ out){
  if (threadIdx.x==0){
    float c=0.f,l=0.f;
    for (int n=0;n<NIMG;n++){ c+=g_lossC[n]; l+=g_lossL[n]; }
    out[(size_t)NIMG*POST*7 + 0] = c / 2048.f;
    out[(size_t)NIMG*POST*7 + 1] = l / 2048.f;
  }
}

extern "C" void kernel_launch(void* const* d_in, const int* in_sizes, int n_in,
                              void* d_out, int out_size){
  const float* anchors = (const float*)d_in[0];
  const float* pi      = (const float*)d_in[1];
  const float* mu      = (const float*)d_in[2];
  const float* sigma   = (const float*)d_in[3];
  const float* deltas  = (const float*)d_in[4];
  const float* gt      = (const float*)d_in[5];
  float* out = (float*)d_out;
  (void)in_sizes; (void)n_in; (void)out_size;

  k_init<<<8,1024>>>();
  k_fused<<<NIMG*BPI,256>>>(pi,mu);
  k_iou1<<<NIMG*BPI,256>>>(anchors,gt);
  k_iou2<<<NIMG*BPI,256>>>(anchors,gt);
  k_hist<0><<<NIMG*BPI,256>>>();  k_scanhist<0><<<1,32>>>();
  k_hist<1><<<NIMG*BPI,256>>>();  k_scanhist<1><<<1,32>>>();
  k_hist<2><<<NIMG*BPI,256>>>();  k_scanhist<2><<<1,32>>>();
  k_hist<3><<<NIMG*BPI,256>>>();  k_scanhist<3><<<1,32>>>();
  k_gather<<<NIMG*BPI,256>>>();
  k_fineq<<<1,32>>>();
  k_sort<<<NIMG,1024>>>(anchors,pi,mu,sigma,deltas);
  k_mask<<<NIMG*(PRE/8),256>>>();
  k_greedy<<<NIMG,1024>>>(out);
  k_loss<<<NIMG,1024>>>(anchors,pi,mu,sigma,deltas,gt);
  k_wloss<<<1,32>>>(out);
}